// round 3
// baseline (speedup 1.0000x reference)
#include <cuda_runtime.h>
#include <cuda_bf16.h>
#include <math.h>
#include <stdint.h>

#define QLEN  2048
#define BSZ   2
#define NH    16
#define DH    64
#define DM    1024
#define KLEN  2048
#define RLEN  2048
#define SCALE 0.125f

typedef unsigned long long ull;

// ---------------- scratch (device globals) ----------------------------------
__device__ float g_Qb[(size_t)BSZ * NH * QLEN * DH];   // Q + r_r_bias, (b,n,q,d)
__device__ float g_K [(size_t)BSZ * NH * KLEN * DH];   // (b,n,k,d)
__device__ float g_V [(size_t)BSZ * NH * KLEN * DH];   // (b,n,k,d)
__device__ float g_Rk[(size_t)NH * RLEN * DH];         // (n,r,d)
__device__ float g_BD[(size_t)BSZ * NH * QLEN * RLEN]; // SHIFTED BD (b,n,q,k)
__device__ float g_AV[(size_t)QLEN * BSZ * DM];        // attn_vec (q,b,n*d)
__device__ float g_negmask[(size_t)BSZ * KLEN];        // 0 or -inf, [b][k]

// ---------------- f32x2 helpers ----------------------------------------------
__device__ __forceinline__ ull pack2(float x, float y) {
    ull r; asm("mov.b64 %0, {%1, %2};" : "=l"(r) : "f"(x), "f"(y)); return r;
}
__device__ __forceinline__ ull pdup(float x) { return pack2(x, x); }
__device__ __forceinline__ void ffma2(ull &acc, ull a, ull b) {
    asm("fma.rn.f32x2 %0, %1, %2, %0;" : "+l"(acc) : "l"(a), "l"(b));
}
union PK { ull u; float2 f; };

// ---------------- mask detect + expand ---------------------------------------
__global__ void mask_expand_kernel(const unsigned char* __restrict__ m) {
    __shared__ int cnt[4];
    __shared__ int smode;
    if (threadIdx.x < 4) cnt[threadIdx.x] = 0;
    __syncthreads();
    for (int i = threadIdx.x; i < 4096; i += blockDim.x)
        if (m[i]) atomicAdd(&cnt[i & 3], 1);
    __syncthreads();
    if (threadIdx.x == 0) {
        int mode;
        if (cnt[1] == 0 && cnt[2] == 0 && cnt[3] == 0) mode = 0;      // int32
        else if (cnt[0] == 0 && cnt[1] == 0)           mode = 1;      // float32
        else                                           mode = 2;      // bool byte
        smode = mode;
    }
    __syncthreads();
    int mode = smode;
    for (int idx = threadIdx.x; idx < KLEN * BSZ; idx += blockDim.x) {
        bool msk;
        if (mode == 0)      msk = ((const int*)m)[idx] != 0;
        else if (mode == 1) msk = ((const float*)m)[idx] != 0.0f;
        else                msk = m[idx] != 0;
        int k = idx >> 1, b = idx & 1;                // mask layout (k, b)
        g_negmask[b * KLEN + k] = msk ? -INFINITY : 0.0f;
    }
}

// =============================================================================
// NN GEMM body (128x128 tile, BK=8, FFMA2, reg-prefetch). Variadic epilogue.
// =============================================================================
#define NN_GEMM_BODY(Aptr, Bptr, Kdim, Ndim, ...)                               \
    __shared__ ull   As2[8][128];                                               \
    __shared__ float Bs[8][128];                                                \
    int tid = threadIdx.x;                                                      \
    int tx = tid & 15, ty = tid >> 4;                                           \
    int row0 = blockIdx.y * 128, col0 = blockIdx.x * 128;                       \
    ull acc[8][4] = {};                                                         \
    int ar = tid >> 1, ac = (tid & 1) * 4;                                      \
    int br = tid >> 5, bc = (tid & 31) * 4;                                     \
    float4 pa = *(const float4*)&Aptr[(size_t)(row0 + ar) * Kdim + ac];         \
    float4 pb = *(const float4*)&Bptr[(size_t)br * Ndim + col0 + bc];           \
    for (int k0 = 0; k0 < Kdim; k0 += 8) {                                      \
        As2[ac + 0][ar] = pdup(pa.x); As2[ac + 1][ar] = pdup(pa.y);             \
        As2[ac + 2][ar] = pdup(pa.z); As2[ac + 3][ar] = pdup(pa.w);             \
        *(float4*)&Bs[br][bc] = pb;                                             \
        __syncthreads();                                                        \
        if (k0 + 8 < Kdim) {                                                    \
            pa = *(const float4*)&Aptr[(size_t)(row0 + ar) * Kdim + k0 + 8 + ac]; \
            pb = *(const float4*)&Bptr[(size_t)(k0 + 8 + br) * Ndim + col0 + bc]; \
        }                                                                       \
        _Pragma("unroll")                                                       \
        for (int kk = 0; kk < 8; kk++) {                                        \
            ull ad[8], bp[4];                                                   \
            _Pragma("unroll")                                                   \
            for (int i = 0; i < 8; i++) ad[i] = As2[kk][ty * 8 + i];            \
            const ull* bru = (const ull*)&Bs[kk][0];                            \
            _Pragma("unroll")                                                   \
            for (int j = 0; j < 4; j++) bp[j] = bru[tx * 4 + j];                \
            _Pragma("unroll")                                                   \
            for (int i = 0; i < 8; i++)                                         \
                _Pragma("unroll")                                               \
                for (int j = 0; j < 4; j++) ffma2(acc[i][j], ad[i], bp[j]);     \
        }                                                                       \
        __syncthreads();                                                        \
    }                                                                           \
    __VA_ARGS__

// ---------------- GEMM 1: heads = w @ qkv_w -> Qb/K/V ------------------------
__global__ __launch_bounds__(256)
void gemm_qkv_kernel(const float* __restrict__ A, const float* __restrict__ B,
                     const float* __restrict__ rbias) {
    NN_GEMM_BODY(A, B, 1024, 3072, {
        for (int i = 0; i < 8; i++) {
            int m = row0 + ty * 8 + i;
            int q = m >> 1;
            int b = m & 1;
            for (int jp = 0; jp < 4; jp++) {
                PK pk; pk.u = acc[i][jp];
                int c0 = col0 + tx * 8 + jp * 2;
                int sec = c0 >> 10;
                int h = (c0 & 1023) >> 6;
                int d = c0 & 63;
                size_t off = ((size_t)(b * NH + h) * QLEN + q) * DH + d;
                if (sec == 0) {
                    float2 rb = *(const float2*)&rbias[h * 64 + d];
                    float2 v;
                    v.x = pk.f.x + rb.x;
                    v.y = pk.f.y + rb.y;
                    *(float2*)&g_Qb[off] = v;
                } else if (sec == 1) {
                    *(float2*)&g_K[off] = pk.f;
                } else {
                    *(float2*)&g_V[off] = pk.f;
                }
            }
        }
    })
}

// ---------------- GEMM 2: r_head_k = r @ r_net_w -> Rk -----------------------
__global__ __launch_bounds__(256)
void gemm_rnet_kernel(const float* __restrict__ A, const float* __restrict__ B) {
    NN_GEMM_BODY(A, B, 1024, 1024, {
        for (int i = 0; i < 8; i++) {
            int rr = row0 + ty * 8 + i;
            for (int jp = 0; jp < 4; jp++) {
                PK pk; pk.u = acc[i][jp];
                int c0 = col0 + tx * 8 + jp * 2;
                int h = c0 >> 6;
                int d = c0 & 63;
                *(float2*)&g_Rk[((size_t)h * RLEN + rr) * DH + d] = pk.f;
            }
        }
    })
}

// ---------------- GEMM 6: output = attn_vec @ o_w ----------------------------
__global__ __launch_bounds__(256)
void gemm_out_kernel(const float* __restrict__ B, float* __restrict__ out) {
    const float* A = g_AV;
    NN_GEMM_BODY(A, B, 1024, 1024, {
        for (int i = 0; i < 8; i++) {
            int m = row0 + ty * 8 + i;
            for (int jp = 0; jp < 4; jp++) {
                PK pk; pk.u = acc[i][jp];
                int c0 = col0 + tx * 8 + jp * 2;
                *(float2*)&out[(size_t)m * 1024 + c0] = pk.f;
            }
        }
    })
}

// =============================================================================
// NT GEMM body (128x128, K=64, both operands row-major (len x 64))
// =============================================================================
#define NT_GEMM_BODY(Aptr, Bptr, ...)                                           \
    __shared__ ull   As2[8][128];                                               \
    __shared__ float Bs[8][128];                                                \
    int tid = threadIdx.x;                                                      \
    int tx = tid & 15, ty = tid >> 4;                                           \
    int row0 = blockIdx.y * 128, col0 = blockIdx.x * 128;                       \
    ull acc[8][4] = {};                                                         \
    int ar = tid >> 1, ac = (tid & 1) * 4;                                      \
    float4 pa = *(const float4*)&Aptr[(size_t)(row0 + ar) * DH + ac];           \
    float4 pb = *(const float4*)&Bptr[(size_t)(col0 + ar) * DH + ac];           \
    for (int k0 = 0; k0 < DH; k0 += 8) {                                        \
        As2[ac + 0][ar] = pdup(pa.x); As2[ac + 1][ar] = pdup(pa.y);             \
        As2[ac + 2][ar] = pdup(pa.z); As2[ac + 3][ar] = pdup(pa.w);             \
        Bs[ac + 0][ar] = pb.x; Bs[ac + 1][ar] = pb.y;                           \
        Bs[ac + 2][ar] = pb.z; Bs[ac + 3][ar] = pb.w;                           \
        __syncthreads();                                                        \
        if (k0 + 8 < DH) {                                                      \
            pa = *(const float4*)&Aptr[(size_t)(row0 + ar) * DH + k0 + 8 + ac]; \
            pb = *(const float4*)&Bptr[(size_t)(col0 + ar) * DH + k0 + 8 + ac]; \
        }                                                                       \
        _Pragma("unroll")                                                       \
        for (int kk = 0; kk < 8; kk++) {                                        \
            ull ad[8], bp[4];                                                   \
            _Pragma("unroll")                                                   \
            for (int i = 0; i < 8; i++) ad[i] = As2[kk][ty * 8 + i];            \
            const ull* bru = (const ull*)&Bs[kk][0];                            \
            _Pragma("unroll")                                                   \
            for (int j = 0; j < 4; j++) bp[j] = bru[tx * 4 + j];                \
            _Pragma("unroll")                                                   \
            for (int i = 0; i < 8; i++)                                         \
                _Pragma("unroll")                                               \
                for (int j = 0; j < 4; j++) ffma2(acc[i][j], ad[i], bp[j]);     \
        }                                                                       \
        __syncthreads();                                                        \
    }                                                                           \
    __VA_ARGS__

// ---------------- GEMM 3: BD = Qb @ Rk^T, scattered pre-shifted --------------
// raw element (i,r) -> shifted (q,k):
//   r >= 2047-i : q=i,   k=r-2047+i      (main band, k<=q)
//   r <  2047-i : q=i-1, k=r+i+1         (leak band, k>=q+2; dropped if i==0)
// slot k==q+1 is never written; score kernel forces it to 0.
__global__ __launch_bounds__(256)
void gemm_bd_kernel() {
    int z = blockIdx.z;
    int n = z & (NH - 1);
    const float* Aptr = g_Qb + (size_t)z * QLEN * DH;
    const float* Bptr = g_Rk + (size_t)n * RLEN * DH;
    float* BDz = g_BD + (size_t)z * QLEN * RLEN;
    NT_GEMM_BODY(Aptr, Bptr, {
        for (int i = 0; i < 8; i++) {
            int qi = row0 + ty * 8 + i;       // raw row index
            for (int jp = 0; jp < 4; jp++) {
                PK pk; pk.u = acc[i][jp];
                int r0 = col0 + tx * 8 + jp * 2;
                float vv0 = pk.f.x;
                float vv1 = pk.f.y;
                for (int t = 0; t < 2; t++) {
                    int r = r0 + t;
                    float v = t ? vv1 : vv0;
                    if (r >= 2047 - qi) {
                        BDz[(size_t)qi * RLEN + (r - 2047 + qi)] = v;
                    } else if (qi > 0) {
                        BDz[(size_t)(qi - 1) * RLEN + (r + qi + 1)] = v;
                    }
                }
            }
        }
    })
}

// ---------------- GEMM 4: scores = (Q@K^T + BDsh)*scale + negmask ------------
__global__ __launch_bounds__(256)
void gemm_score_kernel(float* __restrict__ cov) {
    int z = blockIdx.z;
    int b = z >> 4;
    const float* Aptr = g_Qb + (size_t)z * QLEN * DH;
    const float* Bptr = g_K + (size_t)z * KLEN * DH;
    const float* BDz = g_BD + (size_t)z * QLEN * RLEN;
    const float* neg = g_negmask + (size_t)b * KLEN;
    float* Cz = cov + (size_t)z * QLEN * KLEN;
    NT_GEMM_BODY(Aptr, Bptr, {
        for (int i = 0; i < 8; i++) {
            int q = row0 + ty * 8 + i;
            for (int jp = 0; jp < 4; jp++) {
                PK pk; pk.u = acc[i][jp];
                int kb = col0 + tx * 8 + jp * 2;
                float2 bd2 = *(const float2*)&BDz[(size_t)q * RLEN + kb];
                float2 ng  = *(const float2*)&neg[kb];
                float bdx = (kb     == q + 1) ? 0.0f : bd2.x;
                float bdy = (kb + 1 == q + 1) ? 0.0f : bd2.y;
                float2 s;
                s.x = (pk.f.x + bdx) * SCALE + ng.x;
                s.y = (pk.f.y + bdy) * SCALE + ng.y;
                *(float2*)&Cz[(size_t)q * KLEN + kb] = s;
            }
        }
    })
}

// ---------------- softmax over k ---------------------------------------------
__global__ __launch_bounds__(256)
void softmax_kernel(float* __restrict__ cov) {
    size_t row = blockIdx.x;
    float* p = cov + row * KLEN;
    int t = threadIdx.x;
    float4 v0 = ((const float4*)p)[t];
    float4 v1 = ((const float4*)p)[t + 256];
    float m = fmaxf(fmaxf(fmaxf(v0.x, v0.y), fmaxf(v0.z, v0.w)),
                    fmaxf(fmaxf(v1.x, v1.y), fmaxf(v1.z, v1.w)));
    __shared__ float sred[8];
#pragma unroll
    for (int o = 16; o; o >>= 1) m = fmaxf(m, __shfl_xor_sync(0xffffffffu, m, o));
    if ((t & 31) == 0) sred[t >> 5] = m;
    __syncthreads();
    if (t < 8) {
        float x = sred[t];
#pragma unroll
        for (int o = 4; o; o >>= 1) x = fmaxf(x, __shfl_xor_sync(0xffu, x, o));
        if (t == 0) sred[0] = x;
    }
    __syncthreads();
    m = sred[0];
    if (m == -INFINITY) {
        float4 zz = make_float4(0.f, 0.f, 0.f, 0.f);
        ((float4*)p)[t] = zz;
        ((float4*)p)[t + 256] = zz;
        return;
    }
    float e0x = __expf(v0.x - m), e0y = __expf(v0.y - m);
    float e0z = __expf(v0.z - m), e0w = __expf(v0.w - m);
    float e1x = __expf(v1.x - m), e1y = __expf(v1.y - m);
    float e1z = __expf(v1.z - m), e1w = __expf(v1.w - m);
    float s = (e0x + e0y) + (e0z + e0w) + (e1x + e1y) + (e1z + e1w);
    __shared__ float ssum[8];
#pragma unroll
    for (int o = 16; o; o >>= 1) s += __shfl_xor_sync(0xffffffffu, s, o);
    if ((t & 31) == 0) ssum[t >> 5] = s;
    __syncthreads();
    if (t < 8) {
        float x = ssum[t];
#pragma unroll
        for (int o = 4; o; o >>= 1) x += __shfl_xor_sync(0xffu, x, o);
        if (t == 0) ssum[0] = x;
    }
    __syncthreads();
    float inv = 1.0f / ssum[0];
    ((float4*)p)[t]       = make_float4(e0x * inv, e0y * inv, e0z * inv, e0w * inv);
    ((float4*)p)[t + 256] = make_float4(e1x * inv, e1y * inv, e1z * inv, e1w * inv);
}

// ---------------- GEMM 5: attn_vec = P @ V (128x64 tiles, FFMA2) -------------
__global__ __launch_bounds__(256)
void gemm_pv_kernel(const float* __restrict__ cov) {
    int z = blockIdx.y;
    int b = z >> 4;
    int n = z & (NH - 1);
    const float* P = cov + (size_t)z * QLEN * KLEN;
    const float* Vm = g_V + (size_t)z * KLEN * DH;
    __shared__ ull   As2[8][128];
    __shared__ float Bs[8][64];
    int tid = threadIdx.x;
    int tx = tid & 7, ty = tid >> 3;       // 8 col-groups x 32 row-groups
    int row0 = blockIdx.x * 128;
    ull acc[4][4] = {};                     // 4 rows x 8 cols (4 pairs)
    int ar = tid >> 1, ac = (tid & 1) * 4;
    int vbr = tid >> 4, vbc = (tid & 15) * 4;   // threads<128 load V frag
    float4 pa = *(const float4*)&P[(size_t)(row0 + ar) * KLEN + ac];
    float4 pb;
    if (tid < 128) pb = *(const float4*)&Vm[(size_t)vbr * DH + vbc];
    for (int k0 = 0; k0 < KLEN; k0 += 8) {
        As2[ac + 0][ar] = pdup(pa.x); As2[ac + 1][ar] = pdup(pa.y);
        As2[ac + 2][ar] = pdup(pa.z); As2[ac + 3][ar] = pdup(pa.w);
        if (tid < 128) *(float4*)&Bs[vbr][vbc] = pb;
        __syncthreads();
        if (k0 + 8 < KLEN) {
            pa = *(const float4*)&P[(size_t)(row0 + ar) * KLEN + k0 + 8 + ac];
            if (tid < 128) pb = *(const float4*)&Vm[(size_t)(k0 + 8 + vbr) * DH + vbc];
        }
#pragma unroll
        for (int kk = 0; kk < 8; kk++) {
            ull ad[4], bp[4];
#pragma unroll
            for (int i = 0; i < 4; i++) ad[i] = As2[kk][ty * 4 + i];
            const ull* bru = (const ull*)&Bs[kk][0];
#pragma unroll
            for (int j = 0; j < 4; j++) bp[j] = bru[tx * 4 + j];
#pragma unroll
            for (int i = 0; i < 4; i++)
#pragma unroll
                for (int j = 0; j < 4; j++) ffma2(acc[i][j], ad[i], bp[j]);
        }
        __syncthreads();
    }
    for (int i = 0; i < 4; i++) {
        int q = row0 + ty * 4 + i;
        for (int jp = 0; jp < 4; jp++) {
            PK pk; pk.u = acc[i][jp];
            int d = tx * 8 + jp * 2;
            *(float2*)&g_AV[((size_t)q * BSZ + b) * DM + n * DH + d] = pk.f;
        }
    }
}

// ---------------- launch ------------------------------------------------------
extern "C" void kernel_launch(void* const* d_in, const int* in_sizes, int n_in,
                              void* d_out, int out_size) {
    const float* w       = (const float*)d_in[0];
    const float* r       = (const float*)d_in[1];
    const void*  mask    = d_in[2];
    const float* qkv_w   = (const float*)d_in[3];
    const float* r_net_w = (const float*)d_in[4];
    const float* o_w     = (const float*)d_in[5];
    const float* r_r_bias = (const float*)d_in[7];  // reference bug: r_r_bias used for both

    float* out = (float*)d_out;
    float* cov = out + (size_t)QLEN * BSZ * DM;

    mask_expand_kernel<<<1, 256>>>((const unsigned char*)mask);
    gemm_qkv_kernel<<<dim3(24, 32), 256>>>(w, qkv_w, r_r_bias);
    gemm_rnet_kernel<<<dim3(8, 16), 256>>>(r, r_net_w);
    gemm_bd_kernel<<<dim3(16, 16, BSZ * NH), 256>>>();
    gemm_score_kernel<<<dim3(16, 16, BSZ * NH), 256>>>(cov);
    softmax_kernel<<<BSZ * NH * QLEN, 256>>>(cov);
    gemm_pv_kernel<<<dim3(16, BSZ * NH), 256>>>(cov);
    gemm_out_kernel<<<dim3(8, 32), 256>>>(o_w, out);
}

// round 4
// speedup vs baseline: 1.7506x; 1.7506x over previous
#include <cuda_runtime.h>
#include <cuda_bf16.h>
#include <math.h>
#include <stdint.h>

#define QLEN  2048
#define BSZ   2
#define NH    16
#define DH    64
#define DM    1024
#define KLEN  2048
#define RLEN  2048
#define SCALE 0.125f

// ---------------- scratch (device globals) ----------------------------------
__device__ float g_Qb[(size_t)BSZ * NH * QLEN * DH];   // Q + r_r_bias, (b,n,q,d)
__device__ float g_K [(size_t)BSZ * NH * KLEN * DH];   // (b,n,k,d)
__device__ float g_V [(size_t)BSZ * NH * KLEN * DH];   // (b,n,k,d)
__device__ float g_Rk[(size_t)NH * RLEN * DH];         // (n,r,d)
__device__ float g_BD[(size_t)BSZ * NH * QLEN * RLEN]; // SHIFTED BD (b,n,q,k)
__device__ float g_AV[(size_t)QLEN * BSZ * DM];        // attn_vec (q,b,n*d)
__device__ float g_negmask[(size_t)BSZ * KLEN];        // 0 or -inf, [b][k]

// ---------------- helpers -----------------------------------------------------
__device__ __forceinline__ uint32_t f2tf(float f) {
    uint32_t u; asm("cvt.rna.tf32.f32 %0, %1;" : "=r"(u) : "f"(f)); return u;
}
__device__ __forceinline__ void mma8(float* c, const uint32_t* a, const uint32_t* b) {
    asm volatile(
        "mma.sync.aligned.m16n8k8.row.col.f32.tf32.tf32.f32 "
        "{%0,%1,%2,%3}, {%4,%5,%6,%7}, {%8,%9}, {%0,%1,%2,%3};"
        : "+f"(c[0]), "+f"(c[1]), "+f"(c[2]), "+f"(c[3])
        : "r"(a[0]), "r"(a[1]), "r"(a[2]), "r"(a[3]), "r"(b[0]), "r"(b[1]));
}
// raw BD (qi, r) -> shifted slot (validated round 3)
__device__ __forceinline__ void bd_scatter(float* BDz, int qi, int r, float v) {
    if (r >= 2047 - qi)      BDz[(size_t)qi * RLEN + (r - 2047 + qi)] = v;
    else if (qi > 0)         BDz[(size_t)(qi - 1) * RLEN + (r + qi + 1)] = v;
}

// ---------------- mask detect + expand (validated) ---------------------------
__global__ void mask_expand_kernel(const unsigned char* __restrict__ m) {
    __shared__ int cnt[4];
    __shared__ int smode;
    if (threadIdx.x < 4) cnt[threadIdx.x] = 0;
    __syncthreads();
    for (int i = threadIdx.x; i < 4096; i += blockDim.x)
        if (m[i]) atomicAdd(&cnt[i & 3], 1);
    __syncthreads();
    if (threadIdx.x == 0) {
        int mode;
        if (cnt[1] == 0 && cnt[2] == 0 && cnt[3] == 0) mode = 0;      // int32
        else if (cnt[0] == 0 && cnt[1] == 0)           mode = 1;      // float32
        else                                           mode = 2;      // bool byte
        smode = mode;
    }
    __syncthreads();
    int mode = smode;
    for (int idx = threadIdx.x; idx < KLEN * BSZ; idx += blockDim.x) {
        bool msk;
        if (mode == 0)      msk = ((const int*)m)[idx] != 0;
        else if (mode == 1) msk = ((const float*)m)[idx] != 0.0f;
        else                msk = m[idx] != 0;
        int k = idx >> 1, b = idx & 1;
        g_negmask[b * KLEN + k] = msk ? -INFINITY : 0.0f;
    }
}

// =============================================================================
// NN SIMT GEMMs (round-1 validated fp32 path) for projections
// =============================================================================
__global__ __launch_bounds__(256)
void gemm_qkv_kernel(const float* __restrict__ A, const float* __restrict__ B,
                     const float* __restrict__ rbias) {
    const int K = DM, N = 3 * NH * DH;
    __shared__ float As[8][128];
    __shared__ float Bs[8][128];
    int tid = threadIdx.x;
    int tx = tid & 15, ty = tid >> 4;
    int row0 = blockIdx.y * 128, col0 = blockIdx.x * 128;
    float acc[8][8] = {};
    int ar = tid >> 1, ac = (tid & 1) * 4;
    int br = tid >> 5, bc = (tid & 31) * 4;
    for (int k0 = 0; k0 < K; k0 += 8) {
        float4 av = *(const float4*)&A[(size_t)(row0 + ar) * K + k0 + ac];
        As[ac + 0][ar] = av.x; As[ac + 1][ar] = av.y;
        As[ac + 2][ar] = av.z; As[ac + 3][ar] = av.w;
        *(float4*)&Bs[br][bc] = *(const float4*)&B[(size_t)(k0 + br) * N + col0 + bc];
        __syncthreads();
#pragma unroll
        for (int kk = 0; kk < 8; kk++) {
            float a[8], b[8];
#pragma unroll
            for (int i = 0; i < 8; i++) a[i] = As[kk][ty * 8 + i];
#pragma unroll
            for (int j = 0; j < 8; j++) b[j] = Bs[kk][tx * 8 + j];
#pragma unroll
            for (int i = 0; i < 8; i++)
#pragma unroll
                for (int j = 0; j < 8; j++) acc[i][j] += a[i] * b[j];
        }
        __syncthreads();
    }
#pragma unroll
    for (int i = 0; i < 8; i++) {
        int m = row0 + ty * 8 + i;
        int q = m >> 1, b = m & 1;
#pragma unroll
        for (int j = 0; j < 8; j++) {
            int c = col0 + tx * 8 + j;
            int sec = c >> 10;
            int h = (c & 1023) >> 6;
            int d = c & 63;
            size_t off = ((size_t)(b * NH + h) * QLEN + q) * DH + d;
            float v = acc[i][j];
            if (sec == 0)      g_Qb[off] = v + rbias[h * 64 + d];
            else if (sec == 1) g_K[off] = v;
            else               g_V[off] = v;
        }
    }
}

__global__ __launch_bounds__(256)
void gemm_rnet_kernel(const float* __restrict__ A, const float* __restrict__ B) {
    const int K = DM, N = NH * DH;
    __shared__ float As[8][128];
    __shared__ float Bs[8][128];
    int tid = threadIdx.x;
    int tx = tid & 15, ty = tid >> 4;
    int row0 = blockIdx.y * 128, col0 = blockIdx.x * 128;
    float acc[8][8] = {};
    int ar = tid >> 1, ac = (tid & 1) * 4;
    int br = tid >> 5, bc = (tid & 31) * 4;
    for (int k0 = 0; k0 < K; k0 += 8) {
        float4 av = *(const float4*)&A[(size_t)(row0 + ar) * K + k0 + ac];
        As[ac + 0][ar] = av.x; As[ac + 1][ar] = av.y;
        As[ac + 2][ar] = av.z; As[ac + 3][ar] = av.w;
        *(float4*)&Bs[br][bc] = *(const float4*)&B[(size_t)(k0 + br) * N + col0 + bc];
        __syncthreads();
#pragma unroll
        for (int kk = 0; kk < 8; kk++) {
            float a[8], b[8];
#pragma unroll
            for (int i = 0; i < 8; i++) a[i] = As[kk][ty * 8 + i];
#pragma unroll
            for (int j = 0; j < 8; j++) b[j] = Bs[kk][tx * 8 + j];
#pragma unroll
            for (int i = 0; i < 8; i++)
#pragma unroll
                for (int j = 0; j < 8; j++) acc[i][j] += a[i] * b[j];
        }
        __syncthreads();
    }
#pragma unroll
    for (int i = 0; i < 8; i++) {
        int rr = row0 + ty * 8 + i;
#pragma unroll
        for (int j = 0; j < 8; j++) {
            int c = col0 + tx * 8 + j;
            int h = c >> 6, d = c & 63;
            g_Rk[((size_t)h * RLEN + rr) * DH + d] = acc[i][j];
        }
    }
}

__global__ __launch_bounds__(256)
void gemm_out_kernel(const float* __restrict__ B, float* __restrict__ out) {
    const int K = DM, N = DM;
    const float* A = g_AV;
    __shared__ float As[8][128];
    __shared__ float Bs[8][128];
    int tid = threadIdx.x;
    int tx = tid & 15, ty = tid >> 4;
    int row0 = blockIdx.y * 128, col0 = blockIdx.x * 128;
    float acc[8][8] = {};
    int ar = tid >> 1, ac = (tid & 1) * 4;
    int br = tid >> 5, bc = (tid & 31) * 4;
    for (int k0 = 0; k0 < K; k0 += 8) {
        float4 av = *(const float4*)&A[(size_t)(row0 + ar) * K + k0 + ac];
        As[ac + 0][ar] = av.x; As[ac + 1][ar] = av.y;
        As[ac + 2][ar] = av.z; As[ac + 3][ar] = av.w;
        *(float4*)&Bs[br][bc] = *(const float4*)&B[(size_t)(k0 + br) * N + col0 + bc];
        __syncthreads();
#pragma unroll
        for (int kk = 0; kk < 8; kk++) {
            float a[8], b[8];
#pragma unroll
            for (int i = 0; i < 8; i++) a[i] = As[kk][ty * 8 + i];
#pragma unroll
            for (int j = 0; j < 8; j++) b[j] = Bs[kk][tx * 8 + j];
#pragma unroll
            for (int i = 0; i < 8; i++)
#pragma unroll
                for (int j = 0; j < 8; j++) acc[i][j] += a[i] * b[j];
        }
        __syncthreads();
    }
#pragma unroll
    for (int i = 0; i < 8; i++) {
        int m = row0 + ty * 8 + i;
#pragma unroll
        for (int j = 0; j < 8; j++) {
            int c = col0 + tx * 8 + j;
            out[(size_t)m * N + c] = acc[i][j];
        }
    }
}

// =============================================================================
// TF32 MMA NT kernels: C[128x128] = A[128x64] @ B[128x64]^T per CTA
// smem stride 68 (bank-conflict-free for m16n8k8 fragment pattern)
// =============================================================================
#define SMEM_STRIDE 68

// ---------------- BD = Qb @ Rk^T, scattered pre-shifted ----------------------
__global__ __launch_bounds__(256)
void bd_mma_kernel() {
    extern __shared__ uint32_t sm[];
    uint32_t (*Qs)[SMEM_STRIDE] = (uint32_t(*)[SMEM_STRIDE])sm;
    uint32_t (*Ks)[SMEM_STRIDE] = (uint32_t(*)[SMEM_STRIDE])(sm + 128 * SMEM_STRIDE);
    int z = blockIdx.z;
    int n = z & (NH - 1);
    const float* Aptr = g_Qb + (size_t)z * QLEN * DH;
    const float* Bptr = g_Rk + (size_t)n * RLEN * DH;
    int row0 = blockIdx.y * 128, col0 = blockIdx.x * 128;
    int tid = threadIdx.x;
#pragma unroll
    for (int i = 0; i < 8; i++) {
        int f4 = tid + i * 256;              // 2048 float4s = 128 rows x 16
        int rw = f4 >> 4, c4 = (f4 & 15) * 4;
        float4 qa = *(const float4*)&Aptr[(size_t)(row0 + rw) * DH + c4];
        float4 kb = *(const float4*)&Bptr[(size_t)(col0 + rw) * DH + c4];
        uint4 qu = make_uint4(f2tf(qa.x), f2tf(qa.y), f2tf(qa.z), f2tf(qa.w));
        uint4 ku = make_uint4(f2tf(kb.x), f2tf(kb.y), f2tf(kb.z), f2tf(kb.w));
        *(uint4*)&Qs[rw][c4] = qu;
        *(uint4*)&Ks[rw][c4] = ku;
    }
    __syncthreads();
    int wid = tid >> 5, lane = tid & 31, g = lane >> 2, t = lane & 3;
    int wm = (wid & 3) * 32, wn = (wid >> 2) * 64;
    float c[2][8][4] = {};
#pragma unroll
    for (int k0 = 0; k0 < 64; k0 += 8) {
        uint32_t a[2][4], b[8][2];
#pragma unroll
        for (int mt = 0; mt < 2; mt++) {
            int r = wm + mt * 16 + g;
            a[mt][0] = Qs[r][k0 + t];     a[mt][1] = Qs[r + 8][k0 + t];
            a[mt][2] = Qs[r][k0 + t + 4]; a[mt][3] = Qs[r + 8][k0 + t + 4];
        }
#pragma unroll
        for (int nt = 0; nt < 8; nt++) {
            int r = wn + nt * 8 + g;
            b[nt][0] = Ks[r][k0 + t];
            b[nt][1] = Ks[r][k0 + t + 4];
        }
#pragma unroll
        for (int mt = 0; mt < 2; mt++)
#pragma unroll
            for (int nt = 0; nt < 8; nt++) mma8(c[mt][nt], a[mt], b[nt]);
    }
    float* BDz = g_BD + (size_t)z * QLEN * RLEN;
#pragma unroll
    for (int mt = 0; mt < 2; mt++) {
        int q0 = row0 + wm + mt * 16 + g;
#pragma unroll
        for (int nt = 0; nt < 8; nt++) {
            int rb = col0 + wn + nt * 8 + 2 * t;
            bd_scatter(BDz, q0,     rb,     c[mt][nt][0]);
            bd_scatter(BDz, q0,     rb + 1, c[mt][nt][1]);
            bd_scatter(BDz, q0 + 8, rb,     c[mt][nt][2]);
            bd_scatter(BDz, q0 + 8, rb + 1, c[mt][nt][3]);
        }
    }
}

// ---------------- scores = (Q@K^T + BDsh)*scale + negmask --------------------
__global__ __launch_bounds__(256)
void score_mma_kernel(float* __restrict__ cov) {
    extern __shared__ uint32_t sm[];
    uint32_t (*Qs)[SMEM_STRIDE] = (uint32_t(*)[SMEM_STRIDE])sm;
    uint32_t (*Ks)[SMEM_STRIDE] = (uint32_t(*)[SMEM_STRIDE])(sm + 128 * SMEM_STRIDE);
    int z = blockIdx.z;
    int b = z >> 4;
    const float* Aptr = g_Qb + (size_t)z * QLEN * DH;
    const float* Bptr = g_K + (size_t)z * KLEN * DH;
    int row0 = blockIdx.y * 128, col0 = blockIdx.x * 128;
    int tid = threadIdx.x;
#pragma unroll
    for (int i = 0; i < 8; i++) {
        int f4 = tid + i * 256;
        int rw = f4 >> 4, c4 = (f4 & 15) * 4;
        float4 qa = *(const float4*)&Aptr[(size_t)(row0 + rw) * DH + c4];
        float4 kb = *(const float4*)&Bptr[(size_t)(col0 + rw) * DH + c4];
        uint4 qu = make_uint4(f2tf(qa.x), f2tf(qa.y), f2tf(qa.z), f2tf(qa.w));
        uint4 ku = make_uint4(f2tf(kb.x), f2tf(kb.y), f2tf(kb.z), f2tf(kb.w));
        *(uint4*)&Qs[rw][c4] = qu;
        *(uint4*)&Ks[rw][c4] = ku;
    }
    __syncthreads();
    int wid = tid >> 5, lane = tid & 31, g = lane >> 2, t = lane & 3;
    int wm = (wid & 3) * 32, wn = (wid >> 2) * 64;
    float c[2][8][4] = {};
#pragma unroll
    for (int k0 = 0; k0 < 64; k0 += 8) {
        uint32_t a[2][4], b2[8][2];
#pragma unroll
        for (int mt = 0; mt < 2; mt++) {
            int r = wm + mt * 16 + g;
            a[mt][0] = Qs[r][k0 + t];     a[mt][1] = Qs[r + 8][k0 + t];
            a[mt][2] = Qs[r][k0 + t + 4]; a[mt][3] = Qs[r + 8][k0 + t + 4];
        }
#pragma unroll
        for (int nt = 0; nt < 8; nt++) {
            int r = wn + nt * 8 + g;
            b2[nt][0] = Ks[r][k0 + t];
            b2[nt][1] = Ks[r][k0 + t + 4];
        }
#pragma unroll
        for (int mt = 0; mt < 2; mt++)
#pragma unroll
            for (int nt = 0; nt < 8; nt++) mma8(c[mt][nt], a[mt], b2[nt]);
    }
    const float* BDz = g_BD + (size_t)z * QLEN * RLEN;
    const float* neg = g_negmask + (size_t)b * KLEN;
    float* Cz = cov + (size_t)z * QLEN * KLEN;
#pragma unroll
    for (int mt = 0; mt < 2; mt++) {
        int q0 = row0 + wm + mt * 16 + g;
#pragma unroll
        for (int nt = 0; nt < 8; nt++) {
            int kb = col0 + wn + nt * 8 + 2 * t;
            float2 ng = *(const float2*)&neg[kb];
#pragma unroll
            for (int rr = 0; rr < 2; rr++) {
                int q = q0 + rr * 8;
                float2 bd2 = *(const float2*)&BDz[(size_t)q * RLEN + kb];
                float bdx = (kb     == q + 1) ? 0.0f : bd2.x;
                float bdy = (kb + 1 == q + 1) ? 0.0f : bd2.y;
                float2 s;
                s.x = (c[mt][nt][rr * 2 + 0] + bdx) * SCALE + ng.x;
                s.y = (c[mt][nt][rr * 2 + 1] + bdy) * SCALE + ng.y;
                *(float2*)&Cz[(size_t)q * KLEN + kb] = s;
            }
        }
    }
}

// ---------------- softmax over k (validated) ---------------------------------
__global__ __launch_bounds__(256)
void softmax_kernel(float* __restrict__ cov) {
    size_t row = blockIdx.x;
    float* p = cov + row * KLEN;
    int t = threadIdx.x;
    float4 v0 = ((const float4*)p)[t];
    float4 v1 = ((const float4*)p)[t + 256];
    float m = fmaxf(fmaxf(fmaxf(v0.x, v0.y), fmaxf(v0.z, v0.w)),
                    fmaxf(fmaxf(v1.x, v1.y), fmaxf(v1.z, v1.w)));
    __shared__ float sred[8];
#pragma unroll
    for (int o = 16; o; o >>= 1) m = fmaxf(m, __shfl_xor_sync(0xffffffffu, m, o));
    if ((t & 31) == 0) sred[t >> 5] = m;
    __syncthreads();
    if (t < 8) {
        float x = sred[t];
#pragma unroll
        for (int o = 4; o; o >>= 1) x = fmaxf(x, __shfl_xor_sync(0xffu, x, o));
        if (t == 0) sred[0] = x;
    }
    __syncthreads();
    m = sred[0];
    if (m == -INFINITY) {
        float4 zz = make_float4(0.f, 0.f, 0.f, 0.f);
        ((float4*)p)[t] = zz;
        ((float4*)p)[t + 256] = zz;
        return;
    }
    float e0x = __expf(v0.x - m), e0y = __expf(v0.y - m);
    float e0z = __expf(v0.z - m), e0w = __expf(v0.w - m);
    float e1x = __expf(v1.x - m), e1y = __expf(v1.y - m);
    float e1z = __expf(v1.z - m), e1w = __expf(v1.w - m);
    float s = (e0x + e0y) + (e0z + e0w) + (e1x + e1y) + (e1z + e1w);
    __shared__ float ssum[8];
#pragma unroll
    for (int o = 16; o; o >>= 1) s += __shfl_xor_sync(0xffffffffu, s, o);
    if ((t & 31) == 0) ssum[t >> 5] = s;
    __syncthreads();
    if (t < 8) {
        float x = ssum[t];
#pragma unroll
        for (int o = 4; o; o >>= 1) x += __shfl_xor_sync(0xffu, x, o);
        if (t == 0) ssum[0] = x;
    }
    __syncthreads();
    float inv = 1.0f / ssum[0];
    ((float4*)p)[t]       = make_float4(e0x * inv, e0y * inv, e0z * inv, e0w * inv);
    ((float4*)p)[t + 256] = make_float4(e1x * inv, e1y * inv, e1z * inv, e1w * inv);
}

// ---------------- PV: attn_vec = P @ V (TF32 MMA, 128x64 tile, BK=64) --------
__global__ __launch_bounds__(256)
void pv_mma_kernel(const float* __restrict__ cov) {
    extern __shared__ uint32_t sm[];
    uint32_t (*Ps)[SMEM_STRIDE] = (uint32_t(*)[SMEM_STRIDE])sm;
    uint32_t (*Vs)[SMEM_STRIDE] = (uint32_t(*)[SMEM_STRIDE])(sm + 128 * SMEM_STRIDE);
    int z = blockIdx.y;
    int b = z >> 4, n = z & (NH - 1);
    const float* P = cov + (size_t)z * QLEN * KLEN;
    const float* Vm = g_V + (size_t)z * KLEN * DH;
    int row0 = blockIdx.x * 128;
    int tid = threadIdx.x;
    int wid = tid >> 5, lane = tid & 31, g = lane >> 2, t = lane & 3;
    int wm = (wid & 3) * 32, wn = (wid >> 2) * 32;
    float c[2][4][4] = {};
    for (int kc = 0; kc < KLEN; kc += 64) {
#pragma unroll
        for (int i = 0; i < 8; i++) {
            int f4 = tid + i * 256;
            int rw = f4 >> 4, c4 = (f4 & 15) * 4;
            float4 v = *(const float4*)&P[(size_t)(row0 + rw) * KLEN + kc + c4];
            *(uint4*)&Ps[rw][c4] = make_uint4(f2tf(v.x), f2tf(v.y), f2tf(v.z), f2tf(v.w));
        }
#pragma unroll
        for (int i = 0; i < 4; i++) {
            int f4 = tid + i * 256;
            int rw = f4 >> 4, c4 = (f4 & 15) * 4;
            float4 v = *(const float4*)&Vm[(size_t)(kc + rw) * DH + c4];
            *(uint4*)&Vs[rw][c4] = make_uint4(f2tf(v.x), f2tf(v.y), f2tf(v.z), f2tf(v.w));
        }
        __syncthreads();
#pragma unroll
        for (int k0 = 0; k0 < 64; k0 += 8) {
            uint32_t a[2][4], b2[4][2];
#pragma unroll
            for (int mt = 0; mt < 2; mt++) {
                int r = wm + mt * 16 + g;
                a[mt][0] = Ps[r][k0 + t];     a[mt][1] = Ps[r + 8][k0 + t];
                a[mt][2] = Ps[r][k0 + t + 4]; a[mt][3] = Ps[r + 8][k0 + t + 4];
            }
#pragma unroll
            for (int nt = 0; nt < 4; nt++) {
                int cn = wn + nt * 8 + g;
                b2[nt][0] = Vs[k0 + t][cn];
                b2[nt][1] = Vs[k0 + t + 4][cn];
            }
#pragma unroll
            for (int mt = 0; mt < 2; mt++)
#pragma unroll
                for (int nt = 0; nt < 4; nt++) mma8(c[mt][nt], a[mt], b2[nt]);
        }
        __syncthreads();
    }
#pragma unroll
    for (int mt = 0; mt < 2; mt++) {
        int q0 = row0 + wm + mt * 16 + g;
#pragma unroll
        for (int nt = 0; nt < 4; nt++) {
            int d = wn + nt * 8 + 2 * t;
#pragma unroll
            for (int rr = 0; rr < 2; rr++) {
                int q = q0 + rr * 8;
                float2 v;
                v.x = c[mt][nt][rr * 2 + 0];
                v.y = c[mt][nt][rr * 2 + 1];
                *(float2*)&g_AV[((size_t)q * BSZ + b) * DM + n * DH + d] = v;
            }
        }
    }
}

// ---------------- launch ------------------------------------------------------
extern "C" void kernel_launch(void* const* d_in, const int* in_sizes, int n_in,
                              void* d_out, int out_size) {
    const float* w       = (const float*)d_in[0];
    const float* r       = (const float*)d_in[1];
    const void*  mask    = d_in[2];
    const float* qkv_w   = (const float*)d_in[3];
    const float* r_net_w = (const float*)d_in[4];
    const float* o_w     = (const float*)d_in[5];
    const float* r_r_bias = (const float*)d_in[7];  // reference bug: r_r_bias for both

    float* out = (float*)d_out;
    float* cov = out + (size_t)QLEN * BSZ * DM;

    const int SMEM_NT = 2 * 128 * SMEM_STRIDE * 4;          // 69632
    const int SMEM_PV = (128 + 64) * SMEM_STRIDE * 4;       // 52224
    static int attr_done = 0;
    if (!attr_done) {
        cudaFuncSetAttribute(bd_mma_kernel,    cudaFuncAttributeMaxDynamicSharedMemorySize, SMEM_NT);
        cudaFuncSetAttribute(score_mma_kernel, cudaFuncAttributeMaxDynamicSharedMemorySize, SMEM_NT);
        cudaFuncSetAttribute(pv_mma_kernel,    cudaFuncAttributeMaxDynamicSharedMemorySize, SMEM_PV);
        attr_done = 1;
    }

    mask_expand_kernel<<<1, 256>>>((const unsigned char*)mask);
    gemm_qkv_kernel<<<dim3(24, 32), 256>>>(w, qkv_w, r_r_bias);
    gemm_rnet_kernel<<<dim3(8, 16), 256>>>(r, r_net_w);
    bd_mma_kernel<<<dim3(16, 16, BSZ * NH), 256, SMEM_NT>>>();
    score_mma_kernel<<<dim3(16, 16, BSZ * NH), 256, SMEM_NT>>>(cov);
    softmax_kernel<<<BSZ * NH * QLEN, 256>>>(cov);
    pv_mma_kernel<<<dim3(16, BSZ * NH), 256, SMEM_PV>>>(cov);
    gemm_out_kernel<<<dim3(8, 32), 256>>>(o_w, out);
}